// round 8
// baseline (speedup 1.0000x reference)
#include <cuda_runtime.h>
#include <math.h>

#define BB 32
#define SS 2048
#define DD 1024
#define ROWS 64
#define CHUNKS (SS / ROWS)      // 32 blocks per batch
#define NBLK (BB * CHUNKS)      // 1024 blocks total — single resident wave
#define BETA_F 0.1f
#define RHO_F 1.0f

// Deterministic per-block partials (no float atomics -> bitwise stable across replays)
__device__ float g_p1[NBLK];
__device__ float g_p2[NBLK];

// ---------------- hot streaming kernel: single-wave grid ----------------
__global__ void __launch_bounds__(256) wdpo_reduce(const float* __restrict__ e1,
                                                   const float* __restrict__ e2,
                                                   const float* __restrict__ w) {
    const int t   = threadIdx.x;            // 0..255, owns float4 column group
    const int blk = blockIdx.x;
    const int b     = blk >> 5;             // / CHUNKS
    const int chunk = blk & (CHUNKS - 1);

    // each thread keeps its 4 w values in registers for the whole block
    const float4 w4 = reinterpret_cast<const float4*>(w)[t];

    const size_t base = ((size_t)b * SS + (size_t)chunk * ROWS) * DD + 4 * (size_t)t;
    const float4* __restrict__ p1 = reinterpret_cast<const float4*>(e1 + base);
    const float4* __restrict__ p2 = reinterpret_cast<const float4*>(e2 + base);

    float s1 = 0.f, s2 = 0.f;
#pragma unroll 8
    for (int r = 0; r < ROWS; r++) {
        const float4 a = p1[(size_t)r * (DD / 4)];
        const float4 c = p2[(size_t)r * (DD / 4)];
        s1 += a.x * w4.x + a.y * w4.y + a.z * w4.z + a.w * w4.w;
        s2 += c.x * w4.x + c.y * w4.y + c.z * w4.z + c.w * w4.w;
    }

    // block reduction: warp shuffle then 8-warp shared fold
    __shared__ float sh1[8], sh2[8];
#pragma unroll
    for (int o = 16; o; o >>= 1) {
        s1 += __shfl_down_sync(0xffffffffu, s1, o);
        s2 += __shfl_down_sync(0xffffffffu, s2, o);
    }
    const int lane = t & 31, wid = t >> 5;
    if (lane == 0) { sh1[wid] = s1; sh2[wid] = s2; }
    __syncthreads();
    if (wid == 0) {
        s1 = (lane < 8) ? sh1[lane] : 0.f;
        s2 = (lane < 8) ? sh2[lane] : 0.f;
#pragma unroll
        for (int o = 4; o; o >>= 1) {
            s1 += __shfl_down_sync(0xffffffffu, s1, o);
            s2 += __shfl_down_sync(0xffffffffu, s2, o);
        }
        if (lane == 0) { g_p1[blk] = s1; g_p2[blk] = s2; }
    }

    // PDL: this CTA's contribution is committed; let the dependent epilogue
    // grid begin launching while remaining CTAs drain.
    cudaTriggerProgrammaticLaunchCompletion();
}

// ---------------- epilogue: primary-independent work BEFORE the dependency ----
__global__ void __launch_bounds__(1024) wdpo_epilogue(const float* __restrict__ w,
                                                      const float* __restrict__ lp1ref,
                                                      const float* __restrict__ lp2ref,
                                                      const float* __restrict__ pref,
                                                      float* __restrict__ out) {
    const int t = threadIdx.x;
    const int lane = t & 31, wid = t >> 5;

    __shared__ float swsq[32];
    __shared__ float s_ind[32];
    __shared__ float s_gns[32];

    // ||w||^2 — reads only the kernel INPUT w, safe before the primary grid
    // finishes; overlaps with the reduce tail under PDL.
    float v = w[t];
    v = v * v;
#pragma unroll
    for (int o = 16; o; o >>= 1) v += __shfl_down_sync(0xffffffffu, v, o);
    if (lane == 0) swsq[wid] = v;
    __syncthreads();
    if (t == 0) {
        float a = 0.f;
#pragma unroll
        for (int i = 0; i < 32; i++) a += swsq[i];
        swsq[0] = a;
    }
    __syncthreads();
    const float wsq = swsq[0];

    // Wait for the primary grid (all partials written & visible).
    cudaGridDependencySynchronize();

    // warp `wid` folds the 32 partials of batch b = wid (deterministic order)
    const int b = wid;
    const int base = b * CHUNKS;
    float s1 = g_p1[base + lane];
    float s2 = g_p2[base + lane];
#pragma unroll
    for (int o = 16; o; o >>= 1) {
        s1 += __shfl_down_sync(0xffffffffu, s1, o);
        s2 += __shfl_down_sync(0xffffffffu, s2, o);
    }
    if (lane == 0) {
        const float h = (s1 - lp1ref[b]) - (s2 - lp2ref[b]);
        const float z = BETA_F * h;
        const float p = pref[b];
        // stable softplus: softplus(x) = max(x,0) + log1p(exp(-|x|))
        const float lp = log1pf(expf(-fabsf(z)));
        const float sp_pos = fmaxf(z, 0.f) + lp;   // softplus(z)  = l2
        const float sp_neg = fmaxf(-z, 0.f) + lp;  // softplus(-z) = l1
        const float ind = p * sp_neg + (1.f - p) * sp_pos;
        const float sig = 1.f / (1.f + expf(-z));
        const float c = BETA_F * (sig - p);
        s_ind[b] = ind;
        s_gns[b] = 2.f * (float)SS * wsq * c * c;
    }
    __syncthreads();
    if (wid == 0) {
        float i = s_ind[lane];
        float g = s_gns[lane];
#pragma unroll
        for (int o = 16; o; o >>= 1) {
            i += __shfl_down_sync(0xffffffffu, i, o);
            g += __shfl_down_sync(0xffffffffu, g, o);
        }
        if (lane == 0) out[0] = i * (1.f / (float)BB) + RHO_F * sqrtf(g * (1.f / (float)BB));
    }
}

extern "C" void kernel_launch(void* const* d_in, const int* in_sizes, int n_in,
                              void* d_out, int out_size) {
    const float* e1     = (const float*)d_in[0];  // emb_a1 (B,S,D)
    const float* e2     = (const float*)d_in[1];  // emb_a2 (B,S,D)
    const float* w      = (const float*)d_in[2];  // w (D,)
    const float* lp1ref = (const float*)d_in[3];  // log_prob_a1_ref (B,)
    const float* lp2ref = (const float*)d_in[4];  // log_prob_a2_ref (B,)
    const float* pref   = (const float*)d_in[5];  // preference (B,)
    float* out          = (float*)d_out;

    wdpo_reduce<<<NBLK, 256>>>(e1, e2, w);

    // Epilogue with programmatic dependent launch: overlaps its launch + wsq
    // phase with the reduce tail.
    cudaLaunchConfig_t cfg = {};
    cfg.gridDim  = dim3(1, 1, 1);
    cfg.blockDim = dim3(1024, 1, 1);
    cfg.dynamicSmemBytes = 0;
    cfg.stream = 0;
    cudaLaunchAttribute attr[1];
    attr[0].id = cudaLaunchAttributeProgrammaticStreamSerialization;
    attr[0].val.programmaticStreamSerializationAllowed = 1;
    cfg.attrs = attr;
    cfg.numAttrs = 1;
    cudaError_t err = cudaLaunchKernelEx(&cfg, wdpo_epilogue, w, lp1ref, lp2ref, pref, out);
    if (err != cudaSuccess) {
        // Fallback: plain launch (identical semantics, no overlap)
        wdpo_epilogue<<<1, 1024>>>(w, lp1ref, lp2ref, pref, out);
    }
}